// round 15
// baseline (speedup 1.0000x reference)
#include <cuda_runtime.h>
#include <math.h>
#include <mma.h>

using namespace nvcuda;

#define BB     4
#define TT     2048
#define NTOK   (BB*TT)          // 8192
#define DM     128
#define NH     4
#define DH     32
#define WIN    64
#define DFFN   256
#define DQKV   384
#define TILE   16               // tokens per block in k_pre
#define NBLK   (NTOK/TILE)      // 512
#define TILE2  32               // tokens per block in k_post
#define NBLK2  (NTOK/TILE2)     // 256

// k_post dynamic shared: A[32*128] + Bv[32*128] + C[32*256] + Wbuf[8192] + mu/rs
#define WBUF_ELEMS 8192
#define SMEM_POST ((4096 + 4096 + 8192 + WBUF_ELEMS + 64) * 4)

// Scratch (no cudaMalloc allowed)
__device__ float g_h[NTOK*DM];       // 4 MB
__device__ float g_qkv[NTOK*DQKV];   // 12 MB
__device__ float g_att[NTOK*DM];     // 4 MB

// ===========================================================================
// Kernel 1: in_proj (concat->Lin16x128->ReLU->Lin128x128 + PE) + QKV layer 0
// (byte-identical to measured 340us version)
// ===========================================================================
__global__ void __launch_bounds__(256, 4)
k_pre(const float* __restrict__ E,  const float* __restrict__ rho,
      const float* __restrict__ W1, const float* __restrict__ b1,
      const float* __restrict__ W2, const float* __restrict__ b2,
      const float* __restrict__ Wq, const float* __restrict__ bq)
{
    __shared__ float xs[TILE][16];
    __shared__ float sHid[TILE][DM];
    __shared__ float sH[TILE][DM];
    int t = threadIdx.x;
    int m0 = blockIdx.x * TILE;

    {
        int m = t >> 4, k = t & 15;
        int r = m0 + m;
        xs[m][k] = (k < 8) ? E[r*8 + k] : rho[r*8 + (k-8)];
    }
    __syncthreads();

    int g = t >> 7, c = t & 127;
    int mb = g * 8;

    // hidden = relu(x @ W1 + b1)
    {
        float acc[8];
        float bv = b1[c];
        #pragma unroll
        for (int m = 0; m < 8; m++) acc[m] = bv;
        #pragma unroll
        for (int k0 = 0; k0 < 16; k0 += 4) {
            float w0 = W1[(k0+0)*DM + c];
            float w1 = W1[(k0+1)*DM + c];
            float w2 = W1[(k0+2)*DM + c];
            float w3 = W1[(k0+3)*DM + c];
            #pragma unroll
            for (int m = 0; m < 8; m++) {
                float4 x = *(const float4*)&xs[mb+m][k0];
                acc[m] = fmaf(x.x, w0, fmaf(x.y, w1, fmaf(x.z, w2, fmaf(x.w, w3, acc[m]))));
            }
        }
        #pragma unroll
        for (int m = 0; m < 8; m++) sHid[mb+m][c] = fmaxf(acc[m], 0.0f);
    }
    __syncthreads();

    // h = hidden @ W2 + b2 + PE
    {
        float acc[8];
        float bv = b2[c];
        #pragma unroll
        for (int m = 0; m < 8; m++) acc[m] = bv;
        #pragma unroll 4
        for (int k0 = 0; k0 < DM; k0 += 4) {
            float w0 = W2[(k0+0)*DM + c];
            float w1 = W2[(k0+1)*DM + c];
            float w2 = W2[(k0+2)*DM + c];
            float w3 = W2[(k0+3)*DM + c];
            #pragma unroll
            for (int m = 0; m < 8; m++) {
                float4 x = *(const float4*)&sHid[mb+m][k0];
                acc[m] = fmaf(x.x, w0, fmaf(x.y, w1, fmaf(x.z, w2, fmaf(x.w, w3, acc[m]))));
            }
        }
        int i = c >> 1;
        float invf = expf(-9.210340371976184f * (float)i / 64.0f);
        #pragma unroll
        for (int m = 0; m < 8; m++) {
            int r = m0 + mb + m;
            int pos = r & (TT - 1);
            float ang = (float)pos * invf;
            float pe = (c & 1) ? cosf(ang) : sinf(ang);
            float h = acc[m] + pe;
            sH[mb+m][c] = h;
            g_h[r*DM + c] = h;
        }
    }
    __syncthreads();

    // QKV for layer 0
    #pragma unroll
    for (int pass = 0; pass < 3; pass++) {
        int off = pass * DM;
        float acc[8];
        float bv = bq[off + c];
        #pragma unroll
        for (int m = 0; m < 8; m++) acc[m] = bv;
        #pragma unroll 4
        for (int k0 = 0; k0 < DM; k0 += 4) {
            float w0 = Wq[(k0+0)*DQKV + off + c];
            float w1 = Wq[(k0+1)*DQKV + off + c];
            float w2 = Wq[(k0+2)*DQKV + off + c];
            float w3 = Wq[(k0+3)*DQKV + off + c];
            #pragma unroll
            for (int m = 0; m < 8; m++) {
                float4 x = *(const float4*)&sH[mb+m][k0];
                acc[m] = fmaf(x.x, w0, fmaf(x.y, w1, fmaf(x.z, w2, fmaf(x.w, w3, acc[m]))));
            }
        }
        #pragma unroll
        for (int m = 0; m < 8; m++)
            g_qkv[(size_t)(m0+mb+m)*DQKV + off + c] = acc[m];
    }
}

// ===========================================================================
// Kernel 2: tiled banded attention — byte-identical to measured 340us version.
// ===========================================================================
__global__ void __launch_bounds__(256, 4)
k_attn()
{
    int qt = blockIdx.x, h = blockIdx.y, b = blockIdx.z;
    int t = threadIdx.x, w = t >> 5, l = t & 31;
    int qstart = qt * 32;
    int r0 = (qstart >= WIN-1) ? (qstart - (WIN-1)) : 0;
    int nrows = qstart + 32 - r0;           // <= 95

    __shared__ float KT[DH][97];
    __shared__ float Vs[95][DH];
    __shared__ float qs[32][DH];
    __shared__ float ps[8][WIN];

    const float* baseQ = g_qkv + (size_t)(b*TT + qstart)*DQKV + h*DH;
    for (int idx = t; idx < 32*DH; idx += 256) {
        int qi = idx >> 5, d = idx & 31;
        qs[qi][d] = baseQ[qi*DQKV + d];
    }
    const float* baseK = g_qkv + (size_t)(b*TT + r0)*DQKV + DM + h*DH;
    const float* baseV = baseK + DM;
    for (int idx = t; idx < nrows*DH; idx += 256) {
        int r = idx >> 5, d = idx & 31;
        KT[d][r] = baseK[r*DQKV + d];
        Vs[r][d] = baseV[r*DQKV + d];
    }
    __syncthreads();

    const float scale = 0.17677669529663687f;   // 1/sqrt(32)

    #pragma unroll
    for (int s = 0; s < 4; s++) {
        int qi = w*4 + s;
        int iglob = qstart + qi;
        int jlo = (iglob >= WIN-1) ? (iglob - (WIN-1)) : 0;
        int ni = iglob - jlo + 1;           // 1..64
        int base = jlo - r0;                // >= 0, base+63 <= nrows-1

        float a0 = 0.f, a1 = 0.f;
        #pragma unroll
        for (int d = 0; d < DH; d++) {
            float q = qs[qi][d];
            a0 = fmaf(q, KT[d][base + l],      a0);
            a1 = fmaf(q, KT[d][base + l + 32], a1);
        }
        a0 = (l      < ni) ? a0*scale : -1e30f;
        a1 = (l + 32 < ni) ? a1*scale : -1e30f;

        float mx = fmaxf(a0, a1);
        #pragma unroll
        for (int off = 16; off > 0; off >>= 1)
            mx = fmaxf(mx, __shfl_xor_sync(0xffffffffu, mx, off));

        float p0 = (l      < ni) ? __expf(a0 - mx) : 0.0f;
        float p1 = (l + 32 < ni) ? __expf(a1 - mx) : 0.0f;
        ps[w][l]      = p0;
        ps[w][l + 32] = p1;
        float sum = p0 + p1;
        #pragma unroll
        for (int off = 16; off > 0; off >>= 1)
            sum += __shfl_xor_sync(0xffffffffu, sum, off);
        __syncwarp();

        float acc0 = 0.f, acc1 = 0.f, acc2 = 0.f, acc3 = 0.f;
        int j = 0;
        for (; j + 3 < ni; j += 4) {
            acc0 = fmaf(ps[w][j],   Vs[base+j][l],   acc0);
            acc1 = fmaf(ps[w][j+1], Vs[base+j+1][l], acc1);
            acc2 = fmaf(ps[w][j+2], Vs[base+j+2][l], acc2);
            acc3 = fmaf(ps[w][j+3], Vs[base+j+3][l], acc3);
        }
        for (; j < ni; j++)
            acc0 = fmaf(ps[w][j], Vs[base+j][l], acc0);

        float rs = 1.0f / sum;
        g_att[(size_t)(b*TT + iglob)*DM + h*DH + l] = ((acc0+acc1) + (acc2+acc3)) * rs;
        __syncwarp();
    }
}

// ---------------------------------------------------------------------------
// wmma tf32 GEMM with weights staged through shared (coalesced global loads).
// Out[32, N] = As[32, K] @ Wg[K, N(slice)], Wg row stride src_ld.
// Chunk rows = WBUF_ELEMS / N. Accumulators persist across chunks.
// NT tiles of 16 cols per warp; 8 warps cover 32(M) x NT*16*4(N).
// ---------------------------------------------------------------------------
using fragA = wmma::fragment<wmma::matrix_a, 16, 16, 8, wmma::precision::tf32, wmma::row_major>;
using fragB = wmma::fragment<wmma::matrix_b, 16, 16, 8, wmma::precision::tf32, wmma::row_major>;
using fragC = wmma::fragment<wmma::accumulator, 16, 16, 8, float>;

template<int K, int N, int NT>
__device__ __forceinline__ void wgemm_sh(const float* As, int lda,
                                         const float* __restrict__ Wg, int src_ld,
                                         float* Wbuf, float* Out,
                                         int t, int warp)
{
    const int KCH = WBUF_ELEMS / N;              // 64 for N=128, 32 for N=256
    int wm = (warp >> 2) * 16;
    int wn = (warp & 3) * (NT * 16);

    fragC acc[NT];
    #pragma unroll
    for (int u = 0; u < NT; u++) wmma::fill_fragment(acc[u], 0.0f);

    #pragma unroll
    for (int k0 = 0; k0 < K; k0 += KCH) {
        __syncthreads();   // previous chunk's mma reads complete
        #pragma unroll 4
        for (int idx = t; idx < KCH * N; idx += 256) {
            int r = idx / N, cc = idx % N;
            Wbuf[idx] = Wg[(size_t)(k0 + r) * src_ld + cc];
        }
        __syncthreads();

        #pragma unroll
        for (int kk = 0; kk < KCH; kk += 8) {
            fragA a;
            wmma::load_matrix_sync(a, As + (size_t)wm*lda + k0 + kk, lda);
            #pragma unroll
            for (int i = 0; i < a.num_elements; i++) a.x[i] = wmma::__float_to_tf32(a.x[i]);
            #pragma unroll
            for (int u = 0; u < NT; u++) {
                fragB b;
                wmma::load_matrix_sync(b, Wbuf + (size_t)kk*N + wn + u*16, N);
                #pragma unroll
                for (int i = 0; i < b.num_elements; i++) b.x[i] = wmma::__float_to_tf32(b.x[i]);
                wmma::mma_sync(acc[u], a, b, acc[u]);
            }
        }
    }
    #pragma unroll
    for (int u = 0; u < NT; u++)
        wmma::store_matrix_sync(Out + (size_t)wm*N + wn + u*16, acc[u], N, wmma::mem_row_major);
    __syncthreads();
}

// ---------------------------------------------------------------------------
// LayerNorm over 32 tokens (B -> A), 256 threads (8 warps x 4 tokens).
// ---------------------------------------------------------------------------
__device__ __forceinline__ void ln32(const float* B, float* A, float* muS, float* rsS,
                                     const float* __restrict__ gw,
                                     const float* __restrict__ bw, int t)
{
    int w = t >> 5, l = t & 31;
    #pragma unroll
    for (int s = 0; s < 4; s++) {
        int mm = w*4 + s;
        const float* r = B + mm*DM;
        float v = r[l] + r[l+32] + r[l+64] + r[l+96];
        #pragma unroll
        for (int off = 16; off > 0; off >>= 1)
            v += __shfl_xor_sync(0xffffffffu, v, off);
        float mean = v * (1.0f/128.0f);
        float d0 = r[l   ] - mean;
        float d1 = r[l+32] - mean;
        float d2 = r[l+64] - mean;
        float d3 = r[l+96] - mean;
        float q = d0*d0 + d1*d1 + d2*d2 + d3*d3;
        #pragma unroll
        for (int off = 16; off > 0; off >>= 1)
            q += __shfl_xor_sync(0xffffffffu, q, off);
        if (l == 0) { muS[mm] = mean; rsS[mm] = rsqrtf(q * (1.0f/128.0f) + 1e-5f); }
    }
    __syncthreads();
    for (int idx = t; idx < TILE2*DM; idx += 256) {
        int m = idx >> 7, c = idx & 127;
        A[idx] = (B[idx] - muS[m]) * rsS[m] * gw[c] + bw[c];
    }
    __syncthreads();
}

// ===========================================================================
// Kernel 3: fused post-attention block — wmma tf32 with shared-staged weights.
// ===========================================================================
__global__ void __launch_bounds__(256, 2)
k_post(const float* __restrict__ Wo,  const float* __restrict__ bo,
       const float* __restrict__ g1,  const float* __restrict__ b1n,
       const float* __restrict__ Wf1, const float* __restrict__ bf1,
       const float* __restrict__ Wf2, const float* __restrict__ bf2,
       const float* __restrict__ g2,  const float* __restrict__ b2n,
       const float* __restrict__ Wq,  const float* __restrict__ bq,
       const float* __restrict__ Wh,  const float* __restrict__ bh,
       float* __restrict__ out, int last)
{
    extern __shared__ float smem[];
    float* A    = smem;               // [32][128] residual / LN out
    float* Bv   = A + TILE2*DM;       // [32][128] GEMM out / pre-LN
    float* C    = Bv + TILE2*DM;      // [32][256] att staging, then FF hidden
    float* Wbuf = C + TILE2*DFFN;     // [8192] weight staging
    float* muS  = Wbuf + WBUF_ELEMS;
    float* rsS  = muS + TILE2;

    int t = threadIdx.x;
    int warp = t >> 5;
    int m0 = blockIdx.x * TILE2;

    // stage h -> A, att -> C[:,:128] (stride 128)
    for (int idx = t; idx < TILE2*DM; idx += 256) {
        A[idx] = g_h  [(size_t)m0*DM + idx];
        C[idx] = g_att[(size_t)m0*DM + idx];
    }

    // oproj: Bv = att @ Wo   (sync at head of wgemm_sh covers staging)
    wgemm_sh<DM, DM, 2>(C, DM, Wo, DM, Wbuf, Bv, t, warp);
    for (int idx = t; idx < TILE2*DM; idx += 256)
        Bv[idx] += A[idx] + bo[idx & 127];
    __syncthreads();

    ln32(Bv, A, muS, rsS, g1, b1n, t);      // A = LN1 output

    // FF1: C = relu(A @ Wf1 + bf1)
    wgemm_sh<DM, DFFN, 4>(A, DM, Wf1, DFFN, Wbuf, C, t, warp);
    for (int idx = t; idx < TILE2*DFFN; idx += 256)
        C[idx] = fmaxf(C[idx] + bf1[idx & 255], 0.0f);
    __syncthreads();

    // FF2: Bv = C @ Wf2
    wgemm_sh<DFFN, DM, 2>(C, DFFN, Wf2, DM, Wbuf, Bv, t, warp);
    for (int idx = t; idx < TILE2*DM; idx += 256)
        Bv[idx] += A[idx] + bf2[idx & 127];
    __syncthreads();

    ln32(Bv, A, muS, rsS, g2, b2n, t);      // A = LN2 output = new h

    if (!last) {
        for (int idx = t; idx < TILE2*DM; idx += 256)
            g_h[(size_t)m0*DM + idx] = A[idx];

        #pragma unroll
        for (int pass = 0; pass < 3; pass++) {
            int off = pass * DM;
            wgemm_sh<DM, DM, 2>(A, DM, Wq + off, DQKV, Wbuf, Bv, t, warp);
            for (int idx = t; idx < TILE2*DM; idx += 256) {
                int m = idx >> 7, c = idx & 127;
                g_qkv[(size_t)(m0+m)*DQKV + off + c] = Bv[idx] + bq[off + c];
            }
            __syncthreads();
        }
    } else {
        // head: 32 tokens x 8 outputs = 256 values (one per thread)
        int m = t >> 3, cc = t & 7;
        float acc = bh[cc];
        #pragma unroll 8
        for (int k = 0; k < DM; k++)
            acc = fmaf(A[m*DM + k], Wh[k*8 + cc], acc);
        out[(size_t)(m0+m)*8 + cc] = acc;
    }
}

// ===========================================================================
extern "C" void kernel_launch(void* const* d_in, const int* in_sizes, int n_in,
                              void* d_out, int out_size)
{
    const float* E      = (const float*)d_in[0];
    const float* rho    = (const float*)d_in[1];
    const float* W_in1  = (const float*)d_in[2];
    const float* b_in1  = (const float*)d_in[3];
    const float* W_in2  = (const float*)d_in[4];
    const float* b_in2  = (const float*)d_in[5];
    const float* Wqkv   = (const float*)d_in[6];
    const float* bqkv   = (const float*)d_in[7];
    const float* Wo     = (const float*)d_in[8];
    const float* bo     = (const float*)d_in[9];
    const float* ln1g   = (const float*)d_in[10];
    const float* ln1b   = (const float*)d_in[11];
    const float* Wff1   = (const float*)d_in[12];
    const float* bff1   = (const float*)d_in[13];
    const float* Wff2   = (const float*)d_in[14];
    const float* bff2   = (const float*)d_in[15];
    const float* ln2g   = (const float*)d_in[16];
    const float* ln2b   = (const float*)d_in[17];
    const float* W_head = (const float*)d_in[18];
    const float* b_head = (const float*)d_in[19];
    float* out = (float*)d_out;

    static int smem_set = 0;
    if (!smem_set) {
        cudaFuncSetAttribute(k_post, cudaFuncAttributeMaxDynamicSharedMemorySize, SMEM_POST);
        smem_set = 1;
    }

    k_pre<<<NBLK, 256>>>(E, rho, W_in1, b_in1, W_in2, b_in2, Wqkv, bqkv);

    dim3 agrid(TT/32, NH, BB);
    for (int l = 0; l < 3; l++) {
        k_attn<<<agrid, 256>>>();
        int last = (l == 2);
        k_post<<<NBLK2, 256, SMEM_POST>>>(Wo + (size_t)l*DM*DM, bo + l*DM,
                              ln1g + l*DM, ln1b + l*DM,
                              Wff1 + (size_t)l*DM*DFFN, bff1 + l*DFFN,
                              Wff2 + (size_t)l*DFFN*DM, bff2 + l*DM,
                              ln2g + l*DM, ln2b + l*DM,
                              Wqkv + (size_t)(l+1)*DM*DQKV, bqkv + (l+1)*DQKV,
                              W_head, b_head, out, last);
    }
}

// round 16
// speedup vs baseline: 1.9611x; 1.9611x over previous
#include <cuda_runtime.h>
#include <math.h>

#define BB     4
#define TT     2048
#define NTOK   (BB*TT)          // 8192
#define DM     128
#define NH     4
#define DH     32
#define WIN    64
#define DFFN   256
#define DQKV   384
#define TILE   16               // tokens per block in k_pre
#define NBLK   (NTOK/TILE)      // 512
#define TILE2  32               // tokens per block in k_post
#define NBLK2  (NTOK/TILE2)     // 256
#define QT     64               // queries per block in k_attn
#define NROWS  127              // max staged K/V rows (QT + WIN - 1)

// k_post dynamic shared: A[32*128] + B[32*128] + C[32*256] + mu[32] + rs[32]
#define SMEM_POST ((4096 + 4096 + 8192 + 64) * 4)

// Scratch (no cudaMalloc allowed)
__device__ float g_h[NTOK*DM];       // 4 MB
__device__ float g_qkv[NTOK*DQKV];   // 12 MB
__device__ float g_att[NTOK*DM];     // 4 MB

// ===========================================================================
// Kernel 1: in_proj (concat->Lin16x128->ReLU->Lin128x128 + PE) + QKV layer 0
// (byte-identical to measured 340us version)
// ===========================================================================
__global__ void __launch_bounds__(256, 4)
k_pre(const float* __restrict__ E,  const float* __restrict__ rho,
      const float* __restrict__ W1, const float* __restrict__ b1,
      const float* __restrict__ W2, const float* __restrict__ b2,
      const float* __restrict__ Wq, const float* __restrict__ bq)
{
    __shared__ float xs[TILE][16];
    __shared__ float sHid[TILE][DM];
    __shared__ float sH[TILE][DM];
    int t = threadIdx.x;
    int m0 = blockIdx.x * TILE;

    {
        int m = t >> 4, k = t & 15;
        int r = m0 + m;
        xs[m][k] = (k < 8) ? E[r*8 + k] : rho[r*8 + (k-8)];
    }
    __syncthreads();

    int g = t >> 7, c = t & 127;
    int mb = g * 8;

    // hidden = relu(x @ W1 + b1)
    {
        float acc[8];
        float bv = b1[c];
        #pragma unroll
        for (int m = 0; m < 8; m++) acc[m] = bv;
        #pragma unroll
        for (int k0 = 0; k0 < 16; k0 += 4) {
            float w0 = W1[(k0+0)*DM + c];
            float w1 = W1[(k0+1)*DM + c];
            float w2 = W1[(k0+2)*DM + c];
            float w3 = W1[(k0+3)*DM + c];
            #pragma unroll
            for (int m = 0; m < 8; m++) {
                float4 x = *(const float4*)&xs[mb+m][k0];
                acc[m] = fmaf(x.x, w0, fmaf(x.y, w1, fmaf(x.z, w2, fmaf(x.w, w3, acc[m]))));
            }
        }
        #pragma unroll
        for (int m = 0; m < 8; m++) sHid[mb+m][c] = fmaxf(acc[m], 0.0f);
    }
    __syncthreads();

    // h = hidden @ W2 + b2 + PE
    {
        float acc[8];
        float bv = b2[c];
        #pragma unroll
        for (int m = 0; m < 8; m++) acc[m] = bv;
        #pragma unroll 4
        for (int k0 = 0; k0 < DM; k0 += 4) {
            float w0 = W2[(k0+0)*DM + c];
            float w1 = W2[(k0+1)*DM + c];
            float w2 = W2[(k0+2)*DM + c];
            float w3 = W2[(k0+3)*DM + c];
            #pragma unroll
            for (int m = 0; m < 8; m++) {
                float4 x = *(const float4*)&sHid[mb+m][k0];
                acc[m] = fmaf(x.x, w0, fmaf(x.y, w1, fmaf(x.z, w2, fmaf(x.w, w3, acc[m]))));
            }
        }
        int i = c >> 1;
        float invf = expf(-9.210340371976184f * (float)i / 64.0f);
        #pragma unroll
        for (int m = 0; m < 8; m++) {
            int r = m0 + mb + m;
            int pos = r & (TT - 1);
            float ang = (float)pos * invf;
            float pe = (c & 1) ? cosf(ang) : sinf(ang);
            float h = acc[m] + pe;
            sH[mb+m][c] = h;
            g_h[r*DM + c] = h;
        }
    }
    __syncthreads();

    // QKV for layer 0
    #pragma unroll
    for (int pass = 0; pass < 3; pass++) {
        int off = pass * DM;
        float acc[8];
        float bv = bq[off + c];
        #pragma unroll
        for (int m = 0; m < 8; m++) acc[m] = bv;
        #pragma unroll 4
        for (int k0 = 0; k0 < DM; k0 += 4) {
            float w0 = Wq[(k0+0)*DQKV + off + c];
            float w1 = Wq[(k0+1)*DQKV + off + c];
            float w2 = Wq[(k0+2)*DQKV + off + c];
            float w3 = Wq[(k0+3)*DQKV + off + c];
            #pragma unroll
            for (int m = 0; m < 8; m++) {
                float4 x = *(const float4*)&sH[mb+m][k0];
                acc[m] = fmaf(x.x, w0, fmaf(x.y, w1, fmaf(x.z, w2, fmaf(x.w, w3, acc[m]))));
            }
        }
        #pragma unroll
        for (int m = 0; m < 8; m++)
            g_qkv[(size_t)(m0+mb+m)*DQKV + off + c] = acc[m];
    }
}

// ===========================================================================
// Kernel 2: tiled banded attention — 64-query tiles (halved staging/query,
// single wave). Inner per-query loops byte-identical to the 340us version.
// ===========================================================================
__global__ void __launch_bounds__(256, 4)
k_attn()
{
    int qt = blockIdx.x, h = blockIdx.y, b = blockIdx.z;
    int t = threadIdx.x, w = t >> 5, l = t & 31;
    int qstart = qt * QT;
    int r0 = (qstart >= WIN-1) ? (qstart - (WIN-1)) : 0;
    int nrows = qstart + QT - r0;           // <= 127

    __shared__ float KT[DH][NROWS + 2];     // pad 129: conflict-free columns
    __shared__ float Vs[NROWS][DH];
    __shared__ float qs[QT][DH];
    __shared__ float ps[8][WIN];

    const float* baseQ = g_qkv + (size_t)(b*TT + qstart)*DQKV + h*DH;
    for (int idx = t; idx < QT*DH; idx += 256) {
        int qi = idx >> 5, d = idx & 31;
        qs[qi][d] = baseQ[qi*DQKV + d];
    }
    const float* baseK = g_qkv + (size_t)(b*TT + r0)*DQKV + DM + h*DH;
    const float* baseV = baseK + DM;
    for (int idx = t; idx < nrows*DH; idx += 256) {
        int r = idx >> 5, d = idx & 31;
        KT[d][r] = baseK[(size_t)r*DQKV + d];
        Vs[r][d] = baseV[(size_t)r*DQKV + d];
    }
    __syncthreads();

    const float scale = 0.17677669529663687f;   // 1/sqrt(32)

    #pragma unroll
    for (int s = 0; s < 8; s++) {
        int qi = w*8 + s;
        int iglob = qstart + qi;
        int jlo = (iglob >= WIN-1) ? (iglob - (WIN-1)) : 0;
        int ni = iglob - jlo + 1;           // 1..64
        int base = jlo - r0;                // >= 0, base+63 <= nrows-1

        float a0 = 0.f, a1 = 0.f;
        #pragma unroll
        for (int d = 0; d < DH; d++) {
            float q = qs[qi][d];
            a0 = fmaf(q, KT[d][base + l],      a0);
            a1 = fmaf(q, KT[d][base + l + 32], a1);
        }
        a0 = (l      < ni) ? a0*scale : -1e30f;
        a1 = (l + 32 < ni) ? a1*scale : -1e30f;

        float mx = fmaxf(a0, a1);
        #pragma unroll
        for (int off = 16; off > 0; off >>= 1)
            mx = fmaxf(mx, __shfl_xor_sync(0xffffffffu, mx, off));

        float p0 = (l      < ni) ? __expf(a0 - mx) : 0.0f;
        float p1 = (l + 32 < ni) ? __expf(a1 - mx) : 0.0f;
        ps[w][l]      = p0;
        ps[w][l + 32] = p1;
        float sum = p0 + p1;
        #pragma unroll
        for (int off = 16; off > 0; off >>= 1)
            sum += __shfl_xor_sync(0xffffffffu, sum, off);
        __syncwarp();

        float acc0 = 0.f, acc1 = 0.f, acc2 = 0.f, acc3 = 0.f;
        int j = 0;
        for (; j + 3 < ni; j += 4) {
            acc0 = fmaf(ps[w][j],   Vs[base+j][l],   acc0);
            acc1 = fmaf(ps[w][j+1], Vs[base+j+1][l], acc1);
            acc2 = fmaf(ps[w][j+2], Vs[base+j+2][l], acc2);
            acc3 = fmaf(ps[w][j+3], Vs[base+j+3][l], acc3);
        }
        for (; j < ni; j++)
            acc0 = fmaf(ps[w][j], Vs[base+j][l], acc0);

        float rs = 1.0f / sum;
        g_att[(size_t)(b*TT + iglob)*DM + h*DH + l] = ((acc0+acc1) + (acc2+acc3)) * rs;
        __syncwarp();
    }
}

// ---------------------------------------------------------------------------
// 8-token x 2-column scalar GEMM (measured-340us version)
// ---------------------------------------------------------------------------
template<int K, int LD>
__device__ __forceinline__ void gemm8x2(const float* Xb, const float* __restrict__ W,
                                        int wstride, int c0, int c1,
                                        float b0, float b1, float* o0, float* o1)
{
    float a0[8], a1[8];
    #pragma unroll
    for (int m = 0; m < 8; m++) { a0[m] = b0; a1[m] = b1; }
    #pragma unroll 4
    for (int k0 = 0; k0 < K; k0 += 4) {
        const float* wp = W + (size_t)k0*wstride;
        float w00 = wp[c0], w01 = wp[wstride + c0], w02 = wp[2*wstride + c0], w03 = wp[3*wstride + c0];
        float w10 = wp[c1], w11 = wp[wstride + c1], w12 = wp[2*wstride + c1], w13 = wp[3*wstride + c1];
        #pragma unroll
        for (int m = 0; m < 8; m++) {
            float4 x = *(const float4*)(Xb + (size_t)m*LD + k0);
            a0[m] = fmaf(x.x, w00, fmaf(x.y, w01, fmaf(x.z, w02, fmaf(x.w, w03, a0[m]))));
            a1[m] = fmaf(x.x, w10, fmaf(x.y, w11, fmaf(x.z, w12, fmaf(x.w, w13, a1[m]))));
        }
    }
    #pragma unroll
    for (int m = 0; m < 8; m++) { o0[m] = a0[m]; o1[m] = a1[m]; }
}

// ---------------------------------------------------------------------------
// LayerNorm over 32 tokens (B -> A), 256 threads (8 warps x 4 tokens).
// ---------------------------------------------------------------------------
__device__ __forceinline__ void ln32(const float* B, float* A, float* muS, float* rsS,
                                     const float* __restrict__ gw,
                                     const float* __restrict__ bw, int t)
{
    int w = t >> 5, l = t & 31;
    #pragma unroll
    for (int s = 0; s < 4; s++) {
        int mm = w*4 + s;
        const float* r = B + mm*DM;
        float v = r[l] + r[l+32] + r[l+64] + r[l+96];
        #pragma unroll
        for (int off = 16; off > 0; off >>= 1)
            v += __shfl_xor_sync(0xffffffffu, v, off);
        float mean = v * (1.0f/128.0f);
        float d0 = r[l   ] - mean;
        float d1 = r[l+32] - mean;
        float d2 = r[l+64] - mean;
        float d3 = r[l+96] - mean;
        float q = d0*d0 + d1*d1 + d2*d2 + d3*d3;
        #pragma unroll
        for (int off = 16; off > 0; off >>= 1)
            q += __shfl_xor_sync(0xffffffffu, q, off);
        if (l == 0) { muS[mm] = mean; rsS[mm] = rsqrtf(q * (1.0f/128.0f) + 1e-5f); }
    }
    __syncthreads();
    for (int idx = t; idx < TILE2*DM; idx += 256) {
        int m = idx >> 7, c = idx & 127;
        A[idx] = (B[idx] - muS[m]) * rsS[m] * gw[c] + bw[c];
    }
    __syncthreads();
}

// ===========================================================================
// Kernel 3: fused post-attention block (measured-340us scalar version)
// ===========================================================================
__global__ void __launch_bounds__(256, 2)
k_post(const float* __restrict__ Wo,  const float* __restrict__ bo,
       const float* __restrict__ g1,  const float* __restrict__ b1n,
       const float* __restrict__ Wf1, const float* __restrict__ bf1,
       const float* __restrict__ Wf2, const float* __restrict__ bf2,
       const float* __restrict__ g2,  const float* __restrict__ b2n,
       const float* __restrict__ Wq,  const float* __restrict__ bq,
       const float* __restrict__ Wh,  const float* __restrict__ bh,
       float* __restrict__ out, int last)
{
    extern __shared__ float smem[];
    float* A   = smem;              // [32][128] residual / LN out
    float* Bv  = A + TILE2*DM;      // [32][128] pre-LN accumulator
    float* C   = Bv + TILE2*DM;     // [32][256] att staging, then FF hidden
    float* muS = C + TILE2*DFFN;
    float* rsS = muS + TILE2;

    int t = threadIdx.x;
    int m0 = blockIdx.x * TILE2;
    int g  = t >> 6;                // 4 token-groups of 8
    int cp = t & 63;                // column pair: cp, cp+64
    int mb = g * 8;
    float f0[8], f1[8];

    // stage h -> A, att -> C (as [32][128])
    for (int idx = t; idx < TILE2*DM; idx += 256) {
        A[idx] = g_h  [(size_t)m0*DM + idx];
        C[idx] = g_att[(size_t)m0*DM + idx];
    }
    __syncthreads();

    // oproj + residual: B = A + att @ Wo + bo
    gemm8x2<DM,DM>(C + mb*DM, Wo, DM, cp, cp+64, bo[cp], bo[cp+64], f0, f1);
    #pragma unroll
    for (int m = 0; m < 8; m++) {
        int row = (mb+m)*DM;
        Bv[row + cp]      = A[row + cp]      + f0[m];
        Bv[row + cp + 64] = A[row + cp + 64] + f1[m];
    }
    __syncthreads();

    ln32(Bv, A, muS, rsS, g1, b1n, t);      // A = LN1 output

    // FF1: C = relu(A @ Wf1 + bf1), 256 cols in two passes
    gemm8x2<DM,DM>(A + mb*DM, Wf1, DFFN, cp, cp+64, bf1[cp], bf1[cp+64], f0, f1);
    #pragma unroll
    for (int m = 0; m < 8; m++) {
        int row = (mb+m)*DFFN;
        C[row + cp]      = fmaxf(f0[m], 0.0f);
        C[row + cp + 64] = fmaxf(f1[m], 0.0f);
    }
    gemm8x2<DM,DM>(A + mb*DM, Wf1, DFFN, cp+128, cp+192, bf1[cp+128], bf1[cp+192], f0, f1);
    #pragma unroll
    for (int m = 0; m < 8; m++) {
        int row = (mb+m)*DFFN;
        C[row + cp + 128] = fmaxf(f0[m], 0.0f);
        C[row + cp + 192] = fmaxf(f1[m], 0.0f);
    }
    __syncthreads();

    // FF2 + residual: B = A + C @ Wf2 + bf2
    gemm8x2<DFFN,DFFN>(C + mb*DFFN, Wf2, DM, cp, cp+64, bf2[cp], bf2[cp+64], f0, f1);
    #pragma unroll
    for (int m = 0; m < 8; m++) {
        int row = (mb+m)*DM;
        Bv[row + cp]      = A[row + cp]      + f0[m];
        Bv[row + cp + 64] = A[row + cp + 64] + f1[m];
    }
    __syncthreads();

    ln32(Bv, A, muS, rsS, g2, b2n, t);      // A = LN2 output = new h

    if (!last) {
        // write new h + QKV for next layer
        for (int idx = t; idx < TILE2*DM; idx += 256)
            g_h[(size_t)m0*DM + idx] = A[idx];

        #pragma unroll
        for (int pass = 0; pass < 3; pass++) {
            int off = pass * DM;
            gemm8x2<DM,DM>(A + mb*DM, Wq, DQKV, off + cp, off + cp + 64,
                           bq[off + cp], bq[off + cp + 64], f0, f1);
            #pragma unroll
            for (int m = 0; m < 8; m++) {
                size_t row = (size_t)(m0+mb+m)*DQKV + off;
                g_qkv[row + cp]      = f0[m];
                g_qkv[row + cp + 64] = f1[m];
            }
        }
    } else {
        // head: 32 tokens x 8 outputs = 256 values (one per thread)
        int m = t >> 3, cc = t & 7;
        float acc = bh[cc];
        #pragma unroll 8
        for (int k = 0; k < DM; k++)
            acc = fmaf(A[m*DM + k], Wh[k*8 + cc], acc);
        out[(size_t)(m0+m)*8 + cc] = acc;
    }
}

// ===========================================================================
extern "C" void kernel_launch(void* const* d_in, const int* in_sizes, int n_in,
                              void* d_out, int out_size)
{
    const float* E      = (const float*)d_in[0];
    const float* rho    = (const float*)d_in[1];
    const float* W_in1  = (const float*)d_in[2];
    const float* b_in1  = (const float*)d_in[3];
    const float* W_in2  = (const float*)d_in[4];
    const float* b_in2  = (const float*)d_in[5];
    const float* Wqkv   = (const float*)d_in[6];
    const float* bqkv   = (const float*)d_in[7];
    const float* Wo     = (const float*)d_in[8];
    const float* bo     = (const float*)d_in[9];
    const float* ln1g   = (const float*)d_in[10];
    const float* ln1b   = (const float*)d_in[11];
    const float* Wff1   = (const float*)d_in[12];
    const float* bff1   = (const float*)d_in[13];
    const float* Wff2   = (const float*)d_in[14];
    const float* bff2   = (const float*)d_in[15];
    const float* ln2g   = (const float*)d_in[16];
    const float* ln2b   = (const float*)d_in[17];
    const float* W_head = (const float*)d_in[18];
    const float* b_head = (const float*)d_in[19];
    float* out = (float*)d_out;

    static int smem_set = 0;
    if (!smem_set) {
        cudaFuncSetAttribute(k_post, cudaFuncAttributeMaxDynamicSharedMemorySize, SMEM_POST);
        smem_set = 1;
    }

    k_pre<<<NBLK, 256>>>(E, rho, W_in1, b_in1, W_in2, b_in2, Wqkv, bqkv);

    dim3 agrid(TT/QT, NH, BB);
    for (int l = 0; l < 3; l++) {
        k_attn<<<agrid, 256>>>();
        int last = (l == 2);
        k_post<<<NBLK2, 256, SMEM_POST>>>(Wo + (size_t)l*DM*DM, bo + l*DM,
                              ln1g + l*DM, ln1b + l*DM,
                              Wff1 + (size_t)l*DM*DFFN, bff1 + l*DFFN,
                              Wff2 + (size_t)l*DFFN*DM, bff2 + l*DM,
                              ln2g + l*DM, ln2b + l*DM,
                              Wqkv + (size_t)(l+1)*DM*DQKV, bqkv + (l+1)*DQKV,
                              W_head, b_head, out, last);
    }
}

// round 17
// speedup vs baseline: 2.1396x; 1.0910x over previous
#include <cuda_runtime.h>
#include <math.h>

#define BB     4
#define TT     2048
#define NTOK   (BB*TT)          // 8192
#define DM     128
#define NH     4
#define DH     32
#define WIN    64
#define DFFN   256
#define DQKV   384
#define TILE   16               // tokens per block in k_pre
#define NBLK   (NTOK/TILE)      // 512
#define TILE2  32               // tokens per block in k_post
#define NBLK2  (NTOK/TILE2)     // 256

// k_post dynamic shared: A[32*128] + B[32*128] + C[32*256] + mu[32] + rs[32]
#define SMEM_POST ((4096 + 4096 + 8192 + 64) * 4)

// Scratch (no cudaMalloc allowed)
__device__ float g_h[NTOK*DM];       // 4 MB
__device__ float g_qkv[NTOK*DQKV];   // 12 MB
__device__ float g_att[NTOK*DM];     // 4 MB

// ===========================================================================
// Kernel 1: in_proj (concat->Lin16x128->ReLU->Lin128x128 + PE) + QKV layer 0
// (byte-identical to measured 340us version)
// ===========================================================================
__global__ void __launch_bounds__(256, 4)
k_pre(const float* __restrict__ E,  const float* __restrict__ rho,
      const float* __restrict__ W1, const float* __restrict__ b1,
      const float* __restrict__ W2, const float* __restrict__ b2,
      const float* __restrict__ Wq, const float* __restrict__ bq)
{
    __shared__ float xs[TILE][16];
    __shared__ float sHid[TILE][DM];
    __shared__ float sH[TILE][DM];
    int t = threadIdx.x;
    int m0 = blockIdx.x * TILE;

    {
        int m = t >> 4, k = t & 15;
        int r = m0 + m;
        xs[m][k] = (k < 8) ? E[r*8 + k] : rho[r*8 + (k-8)];
    }
    __syncthreads();

    int g = t >> 7, c = t & 127;
    int mb = g * 8;

    // hidden = relu(x @ W1 + b1)
    {
        float acc[8];
        float bv = b1[c];
        #pragma unroll
        for (int m = 0; m < 8; m++) acc[m] = bv;
        #pragma unroll
        for (int k0 = 0; k0 < 16; k0 += 4) {
            float w0 = W1[(k0+0)*DM + c];
            float w1 = W1[(k0+1)*DM + c];
            float w2 = W1[(k0+2)*DM + c];
            float w3 = W1[(k0+3)*DM + c];
            #pragma unroll
            for (int m = 0; m < 8; m++) {
                float4 x = *(const float4*)&xs[mb+m][k0];
                acc[m] = fmaf(x.x, w0, fmaf(x.y, w1, fmaf(x.z, w2, fmaf(x.w, w3, acc[m]))));
            }
        }
        #pragma unroll
        for (int m = 0; m < 8; m++) sHid[mb+m][c] = fmaxf(acc[m], 0.0f);
    }
    __syncthreads();

    // h = hidden @ W2 + b2 + PE
    {
        float acc[8];
        float bv = b2[c];
        #pragma unroll
        for (int m = 0; m < 8; m++) acc[m] = bv;
        #pragma unroll 4
        for (int k0 = 0; k0 < DM; k0 += 4) {
            float w0 = W2[(k0+0)*DM + c];
            float w1 = W2[(k0+1)*DM + c];
            float w2 = W2[(k0+2)*DM + c];
            float w3 = W2[(k0+3)*DM + c];
            #pragma unroll
            for (int m = 0; m < 8; m++) {
                float4 x = *(const float4*)&sHid[mb+m][k0];
                acc[m] = fmaf(x.x, w0, fmaf(x.y, w1, fmaf(x.z, w2, fmaf(x.w, w3, acc[m]))));
            }
        }
        int i = c >> 1;
        float invf = expf(-9.210340371976184f * (float)i / 64.0f);
        #pragma unroll
        for (int m = 0; m < 8; m++) {
            int r = m0 + mb + m;
            int pos = r & (TT - 1);
            float ang = (float)pos * invf;
            float pe = (c & 1) ? cosf(ang) : sinf(ang);
            float h = acc[m] + pe;
            sH[mb+m][c] = h;
            g_h[r*DM + c] = h;
        }
    }
    __syncthreads();

    // QKV for layer 0
    #pragma unroll
    for (int pass = 0; pass < 3; pass++) {
        int off = pass * DM;
        float acc[8];
        float bv = bq[off + c];
        #pragma unroll
        for (int m = 0; m < 8; m++) acc[m] = bv;
        #pragma unroll 4
        for (int k0 = 0; k0 < DM; k0 += 4) {
            float w0 = Wq[(k0+0)*DQKV + off + c];
            float w1 = Wq[(k0+1)*DQKV + off + c];
            float w2 = Wq[(k0+2)*DQKV + off + c];
            float w3 = Wq[(k0+3)*DQKV + off + c];
            #pragma unroll
            for (int m = 0; m < 8; m++) {
                float4 x = *(const float4*)&sH[mb+m][k0];
                acc[m] = fmaf(x.x, w0, fmaf(x.y, w1, fmaf(x.z, w2, fmaf(x.w, w3, acc[m]))));
            }
        }
        #pragma unroll
        for (int m = 0; m < 8; m++)
            g_qkv[(size_t)(m0+mb+m)*DQKV + off + c] = acc[m];
    }
}

// ===========================================================================
// Kernel 2: tiled banded attention — byte-identical to measured 340us version.
// ===========================================================================
__global__ void __launch_bounds__(256, 4)
k_attn()
{
    int qt = blockIdx.x, h = blockIdx.y, b = blockIdx.z;
    int t = threadIdx.x, w = t >> 5, l = t & 31;
    int qstart = qt * 32;
    int r0 = (qstart >= WIN-1) ? (qstart - (WIN-1)) : 0;
    int nrows = qstart + 32 - r0;           // <= 95

    __shared__ float KT[DH][97];
    __shared__ float Vs[95][DH];
    __shared__ float qs[32][DH];
    __shared__ float ps[8][WIN];

    const float* baseQ = g_qkv + (size_t)(b*TT + qstart)*DQKV + h*DH;
    for (int idx = t; idx < 32*DH; idx += 256) {
        int qi = idx >> 5, d = idx & 31;
        qs[qi][d] = baseQ[qi*DQKV + d];
    }
    const float* baseK = g_qkv + (size_t)(b*TT + r0)*DQKV + DM + h*DH;
    const float* baseV = baseK + DM;
    for (int idx = t; idx < nrows*DH; idx += 256) {
        int r = idx >> 5, d = idx & 31;
        KT[d][r] = baseK[r*DQKV + d];
        Vs[r][d] = baseV[r*DQKV + d];
    }
    __syncthreads();

    const float scale = 0.17677669529663687f;   // 1/sqrt(32)

    #pragma unroll
    for (int s = 0; s < 4; s++) {
        int qi = w*4 + s;
        int iglob = qstart + qi;
        int jlo = (iglob >= WIN-1) ? (iglob - (WIN-1)) : 0;
        int ni = iglob - jlo + 1;           // 1..64
        int base = jlo - r0;                // >= 0, base+63 <= nrows-1

        float a0 = 0.f, a1 = 0.f;
        #pragma unroll
        for (int d = 0; d < DH; d++) {
            float q = qs[qi][d];
            a0 = fmaf(q, KT[d][base + l],      a0);
            a1 = fmaf(q, KT[d][base + l + 32], a1);
        }
        a0 = (l      < ni) ? a0*scale : -1e30f;
        a1 = (l + 32 < ni) ? a1*scale : -1e30f;

        float mx = fmaxf(a0, a1);
        #pragma unroll
        for (int off = 16; off > 0; off >>= 1)
            mx = fmaxf(mx, __shfl_xor_sync(0xffffffffu, mx, off));

        float p0 = (l      < ni) ? __expf(a0 - mx) : 0.0f;
        float p1 = (l + 32 < ni) ? __expf(a1 - mx) : 0.0f;
        ps[w][l]      = p0;
        ps[w][l + 32] = p1;
        float sum = p0 + p1;
        #pragma unroll
        for (int off = 16; off > 0; off >>= 1)
            sum += __shfl_xor_sync(0xffffffffu, sum, off);
        __syncwarp();

        float acc0 = 0.f, acc1 = 0.f, acc2 = 0.f, acc3 = 0.f;
        int j = 0;
        for (; j + 3 < ni; j += 4) {
            acc0 = fmaf(ps[w][j],   Vs[base+j][l],   acc0);
            acc1 = fmaf(ps[w][j+1], Vs[base+j+1][l], acc1);
            acc2 = fmaf(ps[w][j+2], Vs[base+j+2][l], acc2);
            acc3 = fmaf(ps[w][j+3], Vs[base+j+3][l], acc3);
        }
        for (; j < ni; j++)
            acc0 = fmaf(ps[w][j], Vs[base+j][l], acc0);

        float rs = 1.0f / sum;
        g_att[(size_t)(b*TT + iglob)*DM + h*DH + l] = ((acc0+acc1) + (acc2+acc3)) * rs;
        __syncwarp();
    }
}

// ---------------------------------------------------------------------------
// 4-token x 4-adjacent-column GEMM: f[m][j] = bias[c0+j] + sum_k X[m][k]*W[k][c0+j]
// Per k-quad: 4 LDG.128 (weights, coalesced) + 4 LDS.128 (broadcast) + 64 FMA.
// ---------------------------------------------------------------------------
template<int K, int LD>
__device__ __forceinline__ void gemm4x4(const float* Xb, const float* __restrict__ W,
                                        int ws, int c0, const float* __restrict__ bias,
                                        float (&f)[4][4])
{
    #pragma unroll
    for (int m = 0; m < 4; m++) {
        f[m][0] = bias[c0+0]; f[m][1] = bias[c0+1];
        f[m][2] = bias[c0+2]; f[m][3] = bias[c0+3];
    }
    #pragma unroll 8
    for (int k0 = 0; k0 < K; k0 += 4) {
        float4 w0 = *(const float4*)(W + (size_t)(k0+0)*ws + c0);
        float4 w1 = *(const float4*)(W + (size_t)(k0+1)*ws + c0);
        float4 w2 = *(const float4*)(W + (size_t)(k0+2)*ws + c0);
        float4 w3 = *(const float4*)(W + (size_t)(k0+3)*ws + c0);
        #pragma unroll
        for (int m = 0; m < 4; m++) {
            float4 x = *(const float4*)(Xb + (size_t)m*LD + k0);
            f[m][0] = fmaf(x.x, w0.x, fmaf(x.y, w1.x, fmaf(x.z, w2.x, fmaf(x.w, w3.x, f[m][0]))));
            f[m][1] = fmaf(x.x, w0.y, fmaf(x.y, w1.y, fmaf(x.z, w2.y, fmaf(x.w, w3.y, f[m][1]))));
            f[m][2] = fmaf(x.x, w0.z, fmaf(x.y, w1.z, fmaf(x.z, w2.z, fmaf(x.w, w3.z, f[m][2]))));
            f[m][3] = fmaf(x.x, w0.w, fmaf(x.y, w1.w, fmaf(x.z, w2.w, fmaf(x.w, w3.w, f[m][3]))));
        }
    }
}

// ---------------------------------------------------------------------------
// LayerNorm over 32 tokens (B -> A), 256 threads (8 warps x 4 tokens).
// ---------------------------------------------------------------------------
__device__ __forceinline__ void ln32(const float* B, float* A, float* muS, float* rsS,
                                     const float* __restrict__ gw,
                                     const float* __restrict__ bw, int t)
{
    int w = t >> 5, l = t & 31;
    #pragma unroll
    for (int s = 0; s < 4; s++) {
        int mm = w*4 + s;
        const float* r = B + mm*DM;
        float v = r[l] + r[l+32] + r[l+64] + r[l+96];
        #pragma unroll
        for (int off = 16; off > 0; off >>= 1)
            v += __shfl_xor_sync(0xffffffffu, v, off);
        float mean = v * (1.0f/128.0f);
        float d0 = r[l   ] - mean;
        float d1 = r[l+32] - mean;
        float d2 = r[l+64] - mean;
        float d3 = r[l+96] - mean;
        float q = d0*d0 + d1*d1 + d2*d2 + d3*d3;
        #pragma unroll
        for (int off = 16; off > 0; off >>= 1)
            q += __shfl_xor_sync(0xffffffffu, q, off);
        if (l == 0) { muS[mm] = mean; rsS[mm] = rsqrtf(q * (1.0f/128.0f) + 1e-5f); }
    }
    __syncthreads();
    for (int idx = t; idx < TILE2*DM; idx += 256) {
        int m = idx >> 7, c = idx & 127;
        A[idx] = (B[idx] - muS[m]) * rsS[m] * gw[c] + bw[c];
    }
    __syncthreads();
}

// ===========================================================================
// Kernel 3: fused post-attention block — 4 tokens x 4 adjacent cols/thread.
// Thread map: g = t>>5 (8 token-groups of 4), ct = t&31, cols c0=4*ct.
// ===========================================================================
__global__ void __launch_bounds__(256, 2)
k_post(const float* __restrict__ Wo,  const float* __restrict__ bo,
       const float* __restrict__ g1,  const float* __restrict__ b1n,
       const float* __restrict__ Wf1, const float* __restrict__ bf1,
       const float* __restrict__ Wf2, const float* __restrict__ bf2,
       const float* __restrict__ g2,  const float* __restrict__ b2n,
       const float* __restrict__ Wq,  const float* __restrict__ bq,
       const float* __restrict__ Wh,  const float* __restrict__ bh,
       float* __restrict__ out, int last)
{
    extern __shared__ float smem[];
    float* A   = smem;              // [32][128] residual / LN out
    float* Bv  = A + TILE2*DM;      // [32][128] pre-LN accumulator
    float* C   = Bv + TILE2*DM;     // [32][256] att staging, then FF hidden
    float* muS = C + TILE2*DFFN;
    float* rsS = muS + TILE2;

    int t = threadIdx.x;
    int m0 = blockIdx.x * TILE2;
    int g  = t >> 5;                // 8 token-groups of 4
    int ct = t & 31;
    int c0 = ct * 4;                // 0..124 (16B aligned)
    int mb = g * 4;
    float f[4][4];

    // stage h -> A, att -> C (as [32][128])
    for (int idx = t; idx < TILE2*DM; idx += 256) {
        A[idx] = g_h  [(size_t)m0*DM + idx];
        C[idx] = g_att[(size_t)m0*DM + idx];
    }
    __syncthreads();

    // oproj + residual: Bv = A + att @ Wo + bo
    gemm4x4<DM,DM>(C + mb*DM, Wo, DM, c0, bo, f);
    #pragma unroll
    for (int m = 0; m < 4; m++) {
        int row = (mb+m)*DM;
        float4 a = *(const float4*)&A[row + c0];
        *(float4*)&Bv[row + c0] = make_float4(a.x + f[m][0], a.y + f[m][1],
                                              a.z + f[m][2], a.w + f[m][3]);
    }
    __syncthreads();

    ln32(Bv, A, muS, rsS, g1, b1n, t);      // A = LN1 output

    // FF1: C = relu(A @ Wf1 + bf1), 256 cols in two passes
    gemm4x4<DM,DM>(A + mb*DM, Wf1, DFFN, c0, bf1, f);
    #pragma unroll
    for (int m = 0; m < 4; m++) {
        int row = (mb+m)*DFFN;
        *(float4*)&C[row + c0] = make_float4(fmaxf(f[m][0],0.f), fmaxf(f[m][1],0.f),
                                             fmaxf(f[m][2],0.f), fmaxf(f[m][3],0.f));
    }
    gemm4x4<DM,DM>(A + mb*DM, Wf1, DFFN, c0 + 128, bf1, f);
    #pragma unroll
    for (int m = 0; m < 4; m++) {
        int row = (mb+m)*DFFN;
        *(float4*)&C[row + c0 + 128] = make_float4(fmaxf(f[m][0],0.f), fmaxf(f[m][1],0.f),
                                                   fmaxf(f[m][2],0.f), fmaxf(f[m][3],0.f));
    }
    __syncthreads();

    // FF2 + residual: Bv = A + C @ Wf2 + bf2
    gemm4x4<DFFN,DFFN>(C + mb*DFFN, Wf2, DM, c0, bf2, f);
    #pragma unroll
    for (int m = 0; m < 4; m++) {
        int row = (mb+m)*DM;
        float4 a = *(const float4*)&A[row + c0];
        *(float4*)&Bv[row + c0] = make_float4(a.x + f[m][0], a.y + f[m][1],
                                              a.z + f[m][2], a.w + f[m][3]);
    }
    __syncthreads();

    ln32(Bv, A, muS, rsS, g2, b2n, t);      // A = LN2 output = new h

    if (!last) {
        // write new h + QKV for next layer
        for (int idx = t; idx < TILE2*DM; idx += 256)
            g_h[(size_t)m0*DM + idx] = A[idx];

        #pragma unroll
        for (int pass = 0; pass < 3; pass++) {
            int off = pass * DM;
            gemm4x4<DM,DM>(A + mb*DM, Wq, DQKV, off + c0, bq, f);
            #pragma unroll
            for (int m = 0; m < 4; m++) {
                size_t row = (size_t)(m0+mb+m)*DQKV;
                *(float4*)&g_qkv[row + off + c0] =
                    make_float4(f[m][0], f[m][1], f[m][2], f[m][3]);
            }
        }
    } else {
        // head: 32 tokens x 8 outputs = 256 values (one per thread)
        int m = t >> 3, cc = t & 7;
        float acc = bh[cc];
        #pragma unroll 8
        for (int k = 0; k < DM; k++)
            acc = fmaf(A[m*DM + k], Wh[k*8 + cc], acc);
        out[(size_t)(m0+m)*8 + cc] = acc;
    }
}

// ===========================================================================
extern "C" void kernel_launch(void* const* d_in, const int* in_sizes, int n_in,
                              void* d_out, int out_size)
{
    const float* E      = (const float*)d_in[0];
    const float* rho    = (const float*)d_in[1];
    const float* W_in1  = (const float*)d_in[2];
    const float* b_in1  = (const float*)d_in[3];
    const float* W_in2  = (const float*)d_in[4];
    const float* b_in2  = (const float*)d_in[5];
    const float* Wqkv   = (const float*)d_in[6];
    const float* bqkv   = (const float*)d_in[7];
    const float* Wo     = (const float*)d_in[8];
    const float* bo     = (const float*)d_in[9];
    const float* ln1g   = (const float*)d_in[10];
    const float* ln1b   = (const float*)d_in[11];
    const float* Wff1   = (const float*)d_in[12];
    const float* bff1   = (const float*)d_in[13];
    const float* Wff2   = (const float*)d_in[14];
    const float* bff2   = (const float*)d_in[15];
    const float* ln2g   = (const float*)d_in[16];
    const float* ln2b   = (const float*)d_in[17];
    const float* W_head = (const float*)d_in[18];
    const float* b_head = (const float*)d_in[19];
    float* out = (float*)d_out;

    static int smem_set = 0;
    if (!smem_set) {
        cudaFuncSetAttribute(k_post, cudaFuncAttributeMaxDynamicSharedMemorySize, SMEM_POST);
        smem_set = 1;
    }

    k_pre<<<NBLK, 256>>>(E, rho, W_in1, b_in1, W_in2, b_in2, Wqkv, bqkv);

    dim3 agrid(TT/32, NH, BB);
    for (int l = 0; l < 3; l++) {
        k_attn<<<agrid, 256>>>();
        int last = (l == 2);
        k_post<<<NBLK2, 256, SMEM_POST>>>(Wo + (size_t)l*DM*DM, bo + l*DM,
                              ln1g + l*DM, ln1b + l*DM,
                              Wff1 + (size_t)l*DM*DFFN, bff1 + l*DFFN,
                              Wff2 + (size_t)l*DFFN*DM, bff2 + l*DM,
                              ln2g + l*DM, ln2b + l*DM,
                              Wqkv + (size_t)(l+1)*DM*DQKV, bqkv + (l+1)*DQKV,
                              W_head, b_head, out, last);
    }
}